// round 1
// baseline (speedup 1.0000x reference)
#include <cuda_runtime.h>
#include <math.h>

// Problem constants
#define BB   32
#define LL   256
#define SS   4
#define DD   512
#define HH   1024      // L*S
#define TGBB 128
#define KD1  2560      // 5*D
#define ND1  2048      // 4*D
#define ND2  512       // D
#define MAXM (BB*HH)   // 32768

#define STATES_ELEMS ((size_t)BB*SS*LL*DD)   // 16777216
#define MASK_ELEMS   ((size_t)BB*SS*LL)      // 32768

// Scratch (device globals; no runtime allocation)
__device__ float g_x[(size_t)MAXM * KD1];   // LN'ed event inputs, compacted rows
__device__ float g_h[(size_t)MAXM * ND1];   // hidden after silu, compacted rows
__device__ int   g_src[MAXM];               // compact row m -> b*H + h
__device__ int   g_dst[MAXM];               // compact row m -> output row (b*S+g)*L + slot
__device__ int   g_count;                   // number of kept tokens
__device__ int   g_kept[BB * SS];           // per (b,group): min(count,L) or 1 if empty
__device__ int   g_emptyf[BB * SS];         // per (b,group): 1 if count==0

__global__ void k_zero() { g_count = 0; }

// ---------------------------------------------------------------------------
// Per-batch bucketization: packed 4x16-bit inclusive scan over H positions.
// One block per batch, 1024 threads (one per history position).
// ---------------------------------------------------------------------------
__global__ void k_build(const int* __restrict__ gids, const int* __restrict__ lengths) {
    int b = blockIdx.x;
    int h = threadIdx.x;
    int len = lengths[b];
    int g = (h < len) ? gids[b * HH + h] : 0;   // invalid -> group 0 (dropped)

    unsigned long long v = (g > 0) ? (1ULL << ((g - 1) * 16)) : 0ULL;

    // warp inclusive scan (64-bit)
    int lane = h & 31, wid = h >> 5;
    #pragma unroll
    for (int o = 1; o < 32; o <<= 1) {
        unsigned long long n = __shfl_up_sync(0xffffffffu, v, o);
        if (lane >= o) v += n;
    }
    __shared__ unsigned long long warpsum[32];
    if (lane == 31) warpsum[wid] = v;
    __syncthreads();
    if (wid == 0) {
        unsigned long long w = warpsum[lane];
        #pragma unroll
        for (int o = 1; o < 32; o <<= 1) {
            unsigned long long n = __shfl_up_sync(0xffffffffu, w, o);
            if (lane >= o) w += n;
        }
        warpsum[lane] = w;
    }
    __syncthreads();
    unsigned long long incl = v + (wid > 0 ? warpsum[wid - 1] : 0ULL);

    __shared__ unsigned long long s_total;
    if (h == HH - 1) s_total = incl;
    __syncthreads();
    unsigned long long tot = s_total;

    if (g > 0) {
        int rank0 = (int)((incl >> ((g - 1) * 16)) & 0xFFFF) - 1;
        int cnt   = (int)((tot  >> ((g - 1) * 16)) & 0xFFFF);
        int off = cnt - LL; if (off < 0) off = 0;
        if (rank0 >= off) {
            int m = atomicAdd(&g_count, 1);
            g_src[m] = b * HH + h;
            g_dst[m] = (b * SS + (g - 1)) * LL + (rank0 - off);
        }
    }
    if (h < SS) {
        int cnt = (int)((tot >> (h * 16)) & 0xFFFF);
        int kept = (cnt == 0) ? 1 : (cnt < LL ? cnt : LL);
        g_kept[b * SS + h] = kept;
        g_emptyf[b * SS + h] = (cnt == 0) ? 1 : 0;
    }
}

// ---------------------------------------------------------------------------
// Initialize output: pos_emb + seq_id_emb (+ empty token) for slots < kept,
// zeros beyond; write mask floats. One block per output row.
// ---------------------------------------------------------------------------
__global__ void k_base(const float* __restrict__ pos_emb, const float* __restrict__ seq_emb,
                       const float* __restrict__ empty_tok, float* __restrict__ out,
                       int write_mask) {
    int r = blockIdx.x;            // (b*S+g)*L + slot
    int slot = r & (LL - 1);
    int bg = r >> 8;               // / L
    int g = bg & (SS - 1);
    int kept = g_kept[bg];
    int tid = threadIdx.x;         // 128 threads, float4 each -> 512 floats

    float4 val = make_float4(0.f, 0.f, 0.f, 0.f);
    if (slot < kept) {
        float4 a = ((const float4*)(pos_emb + (size_t)slot * DD))[tid];
        float4 q = ((const float4*)(seq_emb + (size_t)(g + 1) * DD))[tid];
        val.x = a.x + q.x; val.y = a.y + q.y; val.z = a.z + q.z; val.w = a.w + q.w;
        if (slot == 0 && g_emptyf[bg]) {
            float4 e = ((const float4*)(empty_tok + (size_t)g * DD))[tid];
            val.x += e.x; val.y += e.y; val.z += e.z; val.w += e.w;
        }
    }
    ((float4*)out)[(size_t)r * (DD / 4) + tid] = val;
    if (write_mask && tid == 0)
        out[STATES_ELEMS + r] = (slot < kept) ? 1.0f : 0.0f;
}

// ---------------------------------------------------------------------------
// Gather 5 embeddings (4 token + time-gap) for kept tokens, LayerNorm over 2560.
// One block (256 threads) per compacted token.
// ---------------------------------------------------------------------------
__global__ void k_gather_ln(const float* __restrict__ embed, const float* __restrict__ tg_emb,
                            const float* __restrict__ gamma, const float* __restrict__ beta,
                            const int* __restrict__ ht, const int* __restrict__ pt,
                            const int* __restrict__ at, const int* __restrict__ ct,
                            const int* __restrict__ tgap) {
    int m = blockIdx.x;
    if (m >= g_count) return;
    __shared__ const float* segs[5];
    __shared__ float s_mean, s_rstd;
    int tid = threadIdx.x;

    if (tid == 0) {
        int src = g_src[m];   // kept tokens are always valid positions
        segs[0] = embed + (size_t)ht[src] * DD;
        segs[1] = embed + (size_t)pt[src] * DD;
        segs[2] = embed + (size_t)at[src] * DD;
        segs[3] = embed + (size_t)ct[src] * DD;
        int tg = tgap[src];
        tg = tg < 0 ? 0 : (tg > TGBB ? TGBB : tg);
        segs[4] = tg_emb + (size_t)tg * DD;
    }
    __syncthreads();

    float vals[10];
    float s = 0.f, ss = 0.f;
    #pragma unroll
    for (int k = 0; k < 10; k++) {
        int j = tid + k * 256;
        float v = segs[j >> 9][j & 511];
        vals[k] = v; s += v; ss += v * v;
    }
    #pragma unroll
    for (int o = 16; o > 0; o >>= 1) {
        s  += __shfl_down_sync(0xffffffffu, s,  o);
        ss += __shfl_down_sync(0xffffffffu, ss, o);
    }
    __shared__ float rs[8], rss[8];
    if ((tid & 31) == 0) { rs[tid >> 5] = s; rss[tid >> 5] = ss; }
    __syncthreads();
    if (tid == 0) {
        float S1 = 0.f, S2 = 0.f;
        #pragma unroll
        for (int w = 0; w < 8; w++) { S1 += rs[w]; S2 += rss[w]; }
        float mean = S1 * (1.0f / (float)KD1);
        float var = S2 * (1.0f / (float)KD1) - mean * mean;
        s_mean = mean;
        s_rstd = rsqrtf(var + 1e-5f);
    }
    __syncthreads();
    float mean = s_mean, rstd = s_rstd;
    size_t base = (size_t)m * KD1;
    #pragma unroll
    for (int k = 0; k < 10; k++) {
        int j = tid + k * 256;
        g_x[base + j] = (vals[k] - mean) * rstd * gamma[j] + beta[j];
    }
}

// ---------------------------------------------------------------------------
// SGEMM 128x128x8, 256 threads, 8x8 per thread, float4 everywhere.
// MODE 0: C = silu(g_x @ W + bias) -> g_h      (K=2560, N=2048)
// MODE 1: out[g_dst[m]] += g_h @ W + bias      (K=2048, N=512)  (scatter epilogue)
// ---------------------------------------------------------------------------
template <int MODE>
__global__ __launch_bounds__(256) void k_sgemm(const float* __restrict__ W,
                                               const float* __restrict__ bias,
                                               int K, int N, float* __restrict__ out) {
    int count = g_count;
    int m0 = blockIdx.y * 128;
    if (m0 >= count) return;
    int mEnd = count - m0; if (mEnd > 128) mEnd = 128;

    const float* A = (MODE == 0) ? g_x : g_h;
    const float* Aptr = A + (size_t)m0 * K;
    const float* Bptr = W + (size_t)blockIdx.x * 128;

    __shared__ float As[8][128];
    __shared__ float Bs[8][128];

    int tid = threadIdx.x;
    int aRow = tid >> 1, aCol = (tid & 1) << 2;    // A: 128x8 tile, one float4/thread
    int bRow = tid >> 5, bCol = (tid & 31) << 2;   // B: 8x128 tile, one float4/thread
    int tx = tid & 15, ty = tid >> 4;

    float acc[8][8];
    #pragma unroll
    for (int i = 0; i < 8; i++)
        #pragma unroll
        for (int j = 0; j < 8; j++) acc[i][j] = 0.f;

    for (int k0 = 0; k0 < K; k0 += 8) {
        float4 av = make_float4(0.f, 0.f, 0.f, 0.f);
        if (aRow < mEnd)
            av = *(const float4*)(Aptr + (size_t)aRow * K + k0 + aCol);
        As[aCol + 0][aRow] = av.x;
        As[aCol + 1][aRow] = av.y;
        As[aCol + 2][aRow] = av.z;
        As[aCol + 3][aRow] = av.w;
        float4 bv = *(const float4*)(Bptr + (size_t)(k0 + bRow) * N + bCol);
        *(float4*)(&Bs[bRow][bCol]) = bv;
        __syncthreads();

        #pragma unroll
        for (int kk = 0; kk < 8; kk++) {
            float4 a0 = *(float4*)(&As[kk][ty * 8]);
            float4 a1 = *(float4*)(&As[kk][ty * 8 + 4]);
            float4 b0 = *(float4*)(&Bs[kk][tx * 8]);
            float4 b1 = *(float4*)(&Bs[kk][tx * 8 + 4]);
            float a[8] = {a0.x, a0.y, a0.z, a0.w, a1.x, a1.y, a1.z, a1.w};
            float b[8] = {b0.x, b0.y, b0.z, b0.w, b1.x, b1.y, b1.z, b1.w};
            #pragma unroll
            for (int i = 0; i < 8; i++)
                #pragma unroll
                for (int j = 0; j < 8; j++)
                    acc[i][j] += a[i] * b[j];
        }
        __syncthreads();
    }

    int colBase = blockIdx.x * 128 + tx * 8;
    #pragma unroll
    for (int i = 0; i < 8; i++) {
        int row = ty * 8 + i;
        if (row >= mEnd) continue;
        int m = m0 + row;
        if (MODE == 0) {
            size_t base = (size_t)m * N + colBase;
            #pragma unroll
            for (int j = 0; j < 8; j++) {
                float v = acc[i][j] + bias[colBase + j];
                v = v / (1.0f + expf(-v));   // silu
                g_h[base + j] = v;
            }
        } else {
            int dst = g_dst[m];
            size_t base = (size_t)dst * ND2 + colBase;
            #pragma unroll
            for (int j = 0; j < 8; j++)
                out[base + j] += acc[i][j] + bias[colBase + j];
        }
    }
}

// ---------------------------------------------------------------------------
extern "C" void kernel_launch(void* const* d_in, const int* in_sizes, int n_in,
                              void* d_out, int out_size) {
    const float* embed     = (const float*)d_in[0];
    const float* tg_emb    = (const float*)d_in[1];
    const float* seq_emb   = (const float*)d_in[2];
    const float* pos_emb   = (const float*)d_in[3];
    const float* gamma     = (const float*)d_in[4];
    const float* beta      = (const float*)d_in[5];
    const float* w1        = (const float*)d_in[6];
    const float* b1        = (const float*)d_in[7];
    const float* w2        = (const float*)d_in[8];
    const float* b2        = (const float*)d_in[9];
    const float* empty_tok = (const float*)d_in[10];
    const int*   ht        = (const int*)d_in[11];
    const int*   pt        = (const int*)d_in[12];
    const int*   at        = (const int*)d_in[13];
    const int*   ct        = (const int*)d_in[14];
    const int*   tgap      = (const int*)d_in[15];
    const int*   gids      = (const int*)d_in[16];
    const int*   lengths   = (const int*)d_in[17];
    float* out = (float*)d_out;

    int write_mask = ((size_t)out_size >= STATES_ELEMS + MASK_ELEMS) ? 1 : 0;

    k_zero<<<1, 1>>>();
    k_build<<<BB, HH>>>(gids, lengths);
    k_base<<<BB * SS * LL, 128>>>(pos_emb, seq_emb, empty_tok, out, write_mask);
    k_gather_ln<<<MAXM, 256>>>(embed, tg_emb, gamma, beta, ht, pt, at, ct, tgap);
    k_sgemm<0><<<dim3(ND1 / 128, MAXM / 128), 256>>>(w1, b1, KD1, ND1, nullptr);
    k_sgemm<1><<<dim3(ND2 / 128, MAXM / 128), 256>>>(w2, b2, ND1, ND2, out);
}

// round 3
// speedup vs baseline: 3.2305x; 3.2305x over previous
#include <cuda_runtime.h>
#include <math.h>
#include <stdint.h>

// Problem constants
#define BB   32
#define LL   256
#define SS   4
#define DD   512
#define HH   1024      // L*S
#define TGBB 128
#define KD1  2560      // 5*D
#define ND1  2048      // 4*D
#define ND2  512       // D
#define MAXM (BB*HH)   // 32768

#define STATES_ELEMS ((size_t)BB*SS*LL*DD)   // 16777216
#define MASK_ELEMS   ((size_t)BB*SS*LL)      // 32768

// Scratch (device globals; no runtime allocation)
__device__ float g_x[(size_t)MAXM * KD1];   // LN'ed event inputs (tf32-rounded), compact rows
__device__ float g_h[(size_t)MAXM * ND1];   // hidden after silu (tf32-rounded), compact rows
__device__ float g_w1t[(size_t)ND1 * KD1];  // w1 transposed [N,K], tf32-rounded
__device__ float g_w2t[(size_t)ND2 * ND1];  // w2 transposed [N,K], tf32-rounded
__device__ int   g_src[MAXM];
__device__ int   g_dst[MAXM];
__device__ int   g_count;
__device__ int   g_kept[BB * SS];
__device__ int   g_emptyf[BB * SS];

// ---------------------------------------------------------------------------
// Helpers
// ---------------------------------------------------------------------------
__device__ __forceinline__ uint32_t smem_u32(const void* p) {
    uint32_t a;
    asm("{ .reg .u64 t; cvta.to.shared.u64 t, %1; cvt.u32.u64 %0, t; }" : "=r"(a) : "l"(p));
    return a;
}
__device__ __forceinline__ float tf32r(float x) {
    uint32_t u; asm("cvt.rna.tf32.f32 %0, %1;" : "=r"(u) : "f"(x));
    return __uint_as_float(u);
}
__device__ __forceinline__ void cpasync16(uint32_t dst, const void* src) {
    asm volatile("cp.async.cg.shared.global [%0], [%1], 16;\n" :: "r"(dst), "l"(src));
}
#define CP_COMMIT() asm volatile("cp.async.commit_group;\n" ::: "memory")
#define CP_WAIT3()  asm volatile("cp.async.wait_group 3;\n" ::: "memory")

__device__ __forceinline__ void mma_tf32(float* c, const uint32_t* a, const uint32_t* b) {
    asm volatile(
        "mma.sync.aligned.m16n8k8.row.col.f32.tf32.tf32.f32 "
        "{%0,%1,%2,%3}, {%4,%5,%6,%7}, {%8,%9}, {%0,%1,%2,%3};"
        : "+f"(c[0]), "+f"(c[1]), "+f"(c[2]), "+f"(c[3])
        : "r"(a[0]), "r"(a[1]), "r"(a[2]), "r"(a[3]), "r"(b[0]), "r"(b[1]));
}

__global__ void k_zero() { g_count = 0; }

// ---------------------------------------------------------------------------
// Per-batch bucketization
// ---------------------------------------------------------------------------
__global__ void k_build(const int* __restrict__ gids, const int* __restrict__ lengths) {
    int b = blockIdx.x;
    int h = threadIdx.x;
    int len = lengths[b];
    int g = (h < len) ? gids[b * HH + h] : 0;

    unsigned long long v = (g > 0) ? (1ULL << ((g - 1) * 16)) : 0ULL;
    int lane = h & 31, wid = h >> 5;
    #pragma unroll
    for (int o = 1; o < 32; o <<= 1) {
        unsigned long long n = __shfl_up_sync(0xffffffffu, v, o);
        if (lane >= o) v += n;
    }
    __shared__ unsigned long long warpsum[32];
    if (lane == 31) warpsum[wid] = v;
    __syncthreads();
    if (wid == 0) {
        unsigned long long w = warpsum[lane];
        #pragma unroll
        for (int o = 1; o < 32; o <<= 1) {
            unsigned long long n = __shfl_up_sync(0xffffffffu, w, o);
            if (lane >= o) w += n;
        }
        warpsum[lane] = w;
    }
    __syncthreads();
    unsigned long long incl = v + (wid > 0 ? warpsum[wid - 1] : 0ULL);

    __shared__ unsigned long long s_total;
    if (h == HH - 1) s_total = incl;
    __syncthreads();
    unsigned long long tot = s_total;

    if (g > 0) {
        int rank0 = (int)((incl >> ((g - 1) * 16)) & 0xFFFF) - 1;
        int cnt   = (int)((tot  >> ((g - 1) * 16)) & 0xFFFF);
        int off = cnt - LL; if (off < 0) off = 0;
        if (rank0 >= off) {
            int m = atomicAdd(&g_count, 1);
            g_src[m] = b * HH + h;
            g_dst[m] = (b * SS + (g - 1)) * LL + (rank0 - off);
        }
    }
    if (h < SS) {
        int cnt = (int)((tot >> (h * 16)) & 0xFFFF);
        int kept = (cnt == 0) ? 1 : (cnt < LL ? cnt : LL);
        g_kept[b * SS + h] = kept;
        g_emptyf[b * SS + h] = (cnt == 0) ? 1 : 0;
    }
}

// ---------------------------------------------------------------------------
// Output base init + mask
// ---------------------------------------------------------------------------
__global__ void k_base(const float* __restrict__ pos_emb, const float* __restrict__ seq_emb,
                       const float* __restrict__ empty_tok, float* __restrict__ out,
                       int write_mask) {
    int r = blockIdx.x;
    int slot = r & (LL - 1);
    int bg = r >> 8;
    int g = bg & (SS - 1);
    int kept = g_kept[bg];
    int tid = threadIdx.x;

    float4 val = make_float4(0.f, 0.f, 0.f, 0.f);
    if (slot < kept) {
        float4 a = ((const float4*)(pos_emb + (size_t)slot * DD))[tid];
        float4 q = ((const float4*)(seq_emb + (size_t)(g + 1) * DD))[tid];
        val.x = a.x + q.x; val.y = a.y + q.y; val.z = a.z + q.z; val.w = a.w + q.w;
        if (slot == 0 && g_emptyf[bg]) {
            float4 e = ((const float4*)(empty_tok + (size_t)g * DD))[tid];
            val.x += e.x; val.y += e.y; val.z += e.z; val.w += e.w;
        }
    }
    ((float4*)out)[(size_t)r * (DD / 4) + tid] = val;
    if (write_mask && tid == 0)
        out[STATES_ELEMS + r] = (slot < kept) ? 1.0f : 0.0f;
}

// ---------------------------------------------------------------------------
// Weight transpose [K,N] -> [N,K] with tf32 rounding
// ---------------------------------------------------------------------------
__global__ void k_transpose(const float* __restrict__ W, float* __restrict__ Wt, int K, int N) {
    __shared__ float t[32][33];
    int n0 = blockIdx.x * 32, k0 = blockIdx.y * 32;
    int tx = threadIdx.x, ty = threadIdx.y;   // 32 x 8
    #pragma unroll
    for (int j = 0; j < 32; j += 8)
        t[ty + j][tx] = W[(size_t)(k0 + ty + j) * N + n0 + tx];
    __syncthreads();
    #pragma unroll
    for (int j = 0; j < 32; j += 8)
        Wt[(size_t)(n0 + ty + j) * K + k0 + tx] = tf32r(t[tx][ty + j]);
}

// ---------------------------------------------------------------------------
// Gather 5 embeddings + LayerNorm, store tf32-rounded compact rows
// ---------------------------------------------------------------------------
__global__ void k_gather_ln(const float* __restrict__ embed, const float* __restrict__ tg_emb,
                            const float* __restrict__ gamma, const float* __restrict__ beta,
                            const int* __restrict__ ht, const int* __restrict__ pt,
                            const int* __restrict__ at, const int* __restrict__ ct,
                            const int* __restrict__ tgap) {
    int m = blockIdx.x;
    if (m >= g_count) return;
    __shared__ const float* segs[5];
    __shared__ float s_mean, s_rstd;
    int tid = threadIdx.x;

    if (tid == 0) {
        int src = g_src[m];
        segs[0] = embed + (size_t)ht[src] * DD;
        segs[1] = embed + (size_t)pt[src] * DD;
        segs[2] = embed + (size_t)at[src] * DD;
        segs[3] = embed + (size_t)ct[src] * DD;
        int tg = tgap[src];
        tg = tg < 0 ? 0 : (tg > TGBB ? TGBB : tg);
        segs[4] = tg_emb + (size_t)tg * DD;
    }
    __syncthreads();

    float vals[10];
    float s = 0.f, ss = 0.f;
    #pragma unroll
    for (int k = 0; k < 10; k++) {
        int j = tid + k * 256;
        float v = segs[j >> 9][j & 511];
        vals[k] = v; s += v; ss += v * v;
    }
    #pragma unroll
    for (int o = 16; o > 0; o >>= 1) {
        s  += __shfl_down_sync(0xffffffffu, s,  o);
        ss += __shfl_down_sync(0xffffffffu, ss, o);
    }
    __shared__ float rs[8], rss[8];
    if ((tid & 31) == 0) { rs[tid >> 5] = s; rss[tid >> 5] = ss; }
    __syncthreads();
    if (tid == 0) {
        float S1 = 0.f, S2 = 0.f;
        #pragma unroll
        for (int w = 0; w < 8; w++) { S1 += rs[w]; S2 += rss[w]; }
        float mean = S1 * (1.0f / (float)KD1);
        float var = S2 * (1.0f / (float)KD1) - mean * mean;
        s_mean = mean;
        s_rstd = rsqrtf(var + 1e-5f);
    }
    __syncthreads();
    float mean = s_mean, rstd = s_rstd;
    size_t base = (size_t)m * KD1;
    #pragma unroll
    for (int k = 0; k < 10; k++) {
        int j = tid + k * 256;
        g_x[base + j] = tf32r((vals[k] - mean) * rstd * gamma[j] + beta[j]);
    }
}

// ---------------------------------------------------------------------------
// TF32 mma.sync GEMM: CTA tile 128(M) x 128(N), K-chunk 32, 4-stage cp.async.
// 8 warps, each 64x32 (4 m-tiles x 4 n-tiles of m16n8k8).
// Smem rows padded to 36 floats -> conflict-free fragment LDS.
// MODE 0: g_h = tf32(silu(g_x @ w1 + b1))   K=2560, N=2048
// MODE 1: out[g_dst[m]] += g_h @ w2 + b2    K=2048, N=512
// ---------------------------------------------------------------------------
#define ROWPAD   36                         // floats per smem row (32 + 4 pad)
#define STG_FLTS (128 * ROWPAD * 2)         // A(128x36) + B(128x36) per stage
#define STG_BYTES (STG_FLTS * 4)            // 36864
#define GSMEM_BYTES (4 * STG_BYTES)         // 147456

template <int MODE>
__global__ void __launch_bounds__(256, 1)
k_mma(const float* __restrict__ Bt, const float* __restrict__ bias, float* __restrict__ out) {
    constexpr int K  = MODE ? ND1 : KD1;
    constexpr int N  = MODE ? ND2 : ND1;
    constexpr int NC = K / 32;

    const int count = g_count;
    const int m0 = blockIdx.y * 128;
    if (m0 >= count) return;
    const int n0 = blockIdx.x * 128;
    const float* __restrict__ A = MODE ? g_h : g_x;

    extern __shared__ __align__(16) float sm[];
    const uint32_t sb = smem_u32(sm);
    const int tid = threadIdx.x;
    const int wid = tid >> 5, lane = tid & 31;
    const int wm = wid & 1, wn = wid >> 1;     // 2 x 4 warp grid
    const int g = lane >> 2, tig = lane & 3;
    const int mclamp = count - 1;

    float acc[4][4][4];
    #pragma unroll
    for (int mt = 0; mt < 4; mt++)
        #pragma unroll
        for (int nt = 0; nt < 4; nt++)
            #pragma unroll
            for (int q = 0; q < 4; q++) acc[mt][nt][q] = 0.f;

    auto load_chunk = [&](int c, int st) {
        int kc = c * 32;
        uint32_t aB = sb + st * STG_BYTES;
        uint32_t bB = aB + 128 * ROWPAD * 4;
        #pragma unroll
        for (int j = 0; j < 4; j++) {
            int id = tid + 256 * j;
            int r = id >> 3, cc = id & 7;
            int gr = m0 + r; gr = gr > mclamp ? mclamp : gr;
            cpasync16(aB + r * (ROWPAD * 4) + cc * 16, A + (size_t)gr * K + kc + cc * 4);
        }
        #pragma unroll
        for (int j = 0; j < 4; j++) {
            int id = tid + 256 * j;
            int r = id >> 3, cc = id & 7;
            cpasync16(bB + r * (ROWPAD * 4) + cc * 16, Bt + (size_t)(n0 + r) * K + kc + cc * 4);
        }
    };

    #pragma unroll
    for (int c = 0; c < 3; c++) { load_chunk(c, c); CP_COMMIT(); }

    for (int i = 0; i < NC; i++) {
        if (i + 3 < NC) load_chunk(i + 3, (i + 3) & 3);
        CP_COMMIT();
        CP_WAIT3();
        __syncthreads();

        const float* aS = sm + (size_t)(i & 3) * STG_FLTS;
        const float* bS = aS + 128 * ROWPAD;

        #pragma unroll
        for (int ks = 0; ks < 4; ks++) {
            int kcol = ks * 8 + tig;
            uint32_t afr[4][4];
            uint32_t bfr[4][2];
            #pragma unroll
            for (int mt = 0; mt < 4; mt++) {
                int r = wm * 64 + mt * 16 + g;
                afr[mt][0] = __float_as_uint(aS[r * ROWPAD + kcol]);
                afr[mt][1] = __float_as_uint(aS[(r + 8) * ROWPAD + kcol]);
                afr[mt][2] = __float_as_uint(aS[r * ROWPAD + kcol + 4]);
                afr[mt][3] = __float_as_uint(aS[(r + 8) * ROWPAD + kcol + 4]);
            }
            #pragma unroll
            for (int nt = 0; nt < 4; nt++) {
                int r = wn * 32 + nt * 8 + g;
                bfr[nt][0] = __float_as_uint(bS[r * ROWPAD + kcol]);
                bfr[nt][1] = __float_as_uint(bS[r * ROWPAD + kcol + 4]);
            }
            #pragma unroll
            for (int mt = 0; mt < 4; mt++)
                #pragma unroll
                for (int nt = 0; nt < 4; nt++)
                    mma_tf32(acc[mt][nt], afr[mt], bfr[nt]);
        }
        __syncthreads();
    }

    // ---- epilogue ----
    int dstA[4], dstB[4];
    bool vA[4], vB[4];
    #pragma unroll
    for (int mt = 0; mt < 4; mt++) {
        int r1 = m0 + wm * 64 + mt * 16 + g;
        int r2 = r1 + 8;
        vA[mt] = r1 < count;
        vB[mt] = r2 < count;
        if (MODE == 1) {
            dstA[mt] = vA[mt] ? g_dst[r1] : 0;
            dstB[mt] = vB[mt] ? g_dst[r2] : 0;
        } else {
            dstA[mt] = r1; dstB[mt] = r2;
        }
    }
    #pragma unroll
    for (int nt = 0; nt < 4; nt++) {
        int c = n0 + wn * 32 + nt * 8 + tig * 2;
        float bx = __ldg(&bias[c]), by = __ldg(&bias[c + 1]);
        #pragma unroll
        for (int mt = 0; mt < 4; mt++) {
            if (MODE == 0) {
                if (vA[mt]) {
                    float x = acc[mt][nt][0] + bx, y = acc[mt][nt][1] + by;
                    x = x / (1.0f + expf(-x)); y = y / (1.0f + expf(-y));
                    *(float2*)&g_h[(size_t)dstA[mt] * ND1 + c] = make_float2(tf32r(x), tf32r(y));
                }
                if (vB[mt]) {
                    float x = acc[mt][nt][2] + bx, y = acc[mt][nt][3] + by;
                    x = x / (1.0f + expf(-x)); y = y / (1.0f + expf(-y));
                    *(float2*)&g_h[(size_t)dstB[mt] * ND1 + c] = make_float2(tf32r(x), tf32r(y));
                }
            } else {
                if (vA[mt]) {
                    float2* p = (float2*)&out[(size_t)dstA[mt] * ND2 + c];
                    float2 o = *p;
                    o.x += acc[mt][nt][0] + bx; o.y += acc[mt][nt][1] + by;
                    *p = o;
                }
                if (vB[mt]) {
                    float2* p = (float2*)&out[(size_t)dstB[mt] * ND2 + c];
                    float2 o = *p;
                    o.x += acc[mt][nt][2] + bx; o.y += acc[mt][nt][3] + by;
                    *p = o;
                }
            }
        }
    }
}

// ---------------------------------------------------------------------------
extern "C" void kernel_launch(void* const* d_in, const int* in_sizes, int n_in,
                              void* d_out, int out_size) {
    const float* embed     = (const float*)d_in[0];
    const float* tg_emb    = (const float*)d_in[1];
    const float* seq_emb   = (const float*)d_in[2];
    const float* pos_emb   = (const float*)d_in[3];
    const float* gamma     = (const float*)d_in[4];
    const float* beta      = (const float*)d_in[5];
    const float* w1        = (const float*)d_in[6];
    const float* b1        = (const float*)d_in[7];
    const float* w2        = (const float*)d_in[8];
    const float* b2        = (const float*)d_in[9];
    const float* empty_tok = (const float*)d_in[10];
    const int*   ht        = (const int*)d_in[11];
    const int*   pt        = (const int*)d_in[12];
    const int*   at        = (const int*)d_in[13];
    const int*   ct        = (const int*)d_in[14];
    const int*   tgap      = (const int*)d_in[15];
    const int*   gids      = (const int*)d_in[16];
    const int*   lengths   = (const int*)d_in[17];
    float* out = (float*)d_out;

    int write_mask = ((size_t)out_size >= STATES_ELEMS + MASK_ELEMS) ? 1 : 0;

    float* w1t_p; cudaGetSymbolAddress((void**)&w1t_p, g_w1t);
    float* w2t_p; cudaGetSymbolAddress((void**)&w2t_p, g_w2t);

    cudaFuncSetAttribute(k_mma<0>, cudaFuncAttributeMaxDynamicSharedMemorySize, GSMEM_BYTES);
    cudaFuncSetAttribute(k_mma<1>, cudaFuncAttributeMaxDynamicSharedMemorySize, GSMEM_BYTES);

    k_zero<<<1, 1>>>();
    k_build<<<BB, HH>>>(gids, lengths);
    k_base<<<BB * SS * LL, 128>>>(pos_emb, seq_emb, empty_tok, out, write_mask);
    k_transpose<<<dim3(ND1 / 32, KD1 / 32), dim3(32, 8)>>>(w1, w1t_p, KD1, ND1);
    k_transpose<<<dim3(ND2 / 32, ND1 / 32), dim3(32, 8)>>>(w2, w2t_p, ND1, ND2);
    k_gather_ln<<<MAXM, 256>>>(embed, tg_emb, gamma, beta, ht, pt, at, ct, tgap);
    k_mma<0><<<dim3(ND1 / 128, MAXM / 128), 256, GSMEM_BYTES>>>(w1t_p, b1, nullptr);
    k_mma<1><<<dim3(ND2 / 128, MAXM / 128), 256, GSMEM_BYTES>>>(w2t_p, b2, out);
}

// round 4
// speedup vs baseline: 5.8226x; 1.8023x over previous
#include <cuda_runtime.h>
#include <cuda_fp16.h>
#include <math.h>
#include <stdint.h>

// Problem constants
#define BB   32
#define LL   256
#define SS   4
#define DD   512
#define HH   1024      // L*S
#define TGBB 128
#define KD1  2560      // 5*D
#define ND1  2048      // 4*D
#define ND2  512       // D
#define MAXM (BB*HH)   // 32768

#define STATES_ELEMS ((size_t)BB*SS*LL*DD)   // 16777216
#define MASK_ELEMS   ((size_t)BB*SS*LL)      // 32768

// Scratch (device globals; no runtime allocation)
__device__ __align__(128) __half g_x[(size_t)MAXM * KD1];   // LN'ed inputs, fp16 compact rows
__device__ __align__(128) __half g_h[(size_t)MAXM * ND1];   // hidden after silu, fp16
__device__ __align__(128) __half g_w1t[(size_t)ND1 * KD1];  // w1 transposed [N,K] fp16
__device__ __align__(128) __half g_w2t[(size_t)ND2 * ND1];  // w2 transposed [N,K] fp16
__device__ int   g_src[MAXM];
__device__ int   g_dst[MAXM];
__device__ int   g_count;
__device__ int   g_kept[BB * SS];
__device__ int   g_emptyf[BB * SS];

// ---------------------------------------------------------------------------
// Helpers
// ---------------------------------------------------------------------------
__device__ __forceinline__ uint32_t smem_u32(const void* p) {
    uint32_t a;
    asm("{ .reg .u64 t; cvta.to.shared.u64 t, %1; cvt.u32.u64 %0, t; }" : "=r"(a) : "l"(p));
    return a;
}
__device__ __forceinline__ void cpasync16(uint32_t dst, const void* src) {
    asm volatile("cp.async.cg.shared.global [%0], [%1], 16;\n" :: "r"(dst), "l"(src));
}
#define CP_COMMIT() asm volatile("cp.async.commit_group;\n" ::: "memory")
#define CP_WAIT3()  asm volatile("cp.async.wait_group 3;\n" ::: "memory")

__device__ __forceinline__ void mma_f16(float* c, const uint32_t* a, const uint32_t* b) {
    asm volatile(
        "mma.sync.aligned.m16n8k16.row.col.f32.f16.f16.f32 "
        "{%0,%1,%2,%3}, {%4,%5,%6,%7}, {%8,%9}, {%0,%1,%2,%3};"
        : "+f"(c[0]), "+f"(c[1]), "+f"(c[2]), "+f"(c[3])
        : "r"(a[0]), "r"(a[1]), "r"(a[2]), "r"(a[3]), "r"(b[0]), "r"(b[1]));
}

__global__ void k_zero() { g_count = 0; }

// ---------------------------------------------------------------------------
// Per-batch bucketization
// ---------------------------------------------------------------------------
__global__ void k_build(const int* __restrict__ gids, const int* __restrict__ lengths) {
    int b = blockIdx.x;
    int h = threadIdx.x;
    int len = lengths[b];
    int g = (h < len) ? gids[b * HH + h] : 0;

    unsigned long long v = (g > 0) ? (1ULL << ((g - 1) * 16)) : 0ULL;
    int lane = h & 31, wid = h >> 5;
    #pragma unroll
    for (int o = 1; o < 32; o <<= 1) {
        unsigned long long n = __shfl_up_sync(0xffffffffu, v, o);
        if (lane >= o) v += n;
    }
    __shared__ unsigned long long warpsum[32];
    if (lane == 31) warpsum[wid] = v;
    __syncthreads();
    if (wid == 0) {
        unsigned long long w = warpsum[lane];
        #pragma unroll
        for (int o = 1; o < 32; o <<= 1) {
            unsigned long long n = __shfl_up_sync(0xffffffffu, w, o);
            if (lane >= o) w += n;
        }
        warpsum[lane] = w;
    }
    __syncthreads();
    unsigned long long incl = v + (wid > 0 ? warpsum[wid - 1] : 0ULL);

    __shared__ unsigned long long s_total;
    if (h == HH - 1) s_total = incl;
    __syncthreads();
    unsigned long long tot = s_total;

    if (g > 0) {
        int rank0 = (int)((incl >> ((g - 1) * 16)) & 0xFFFF) - 1;
        int cnt   = (int)((tot  >> ((g - 1) * 16)) & 0xFFFF);
        int off = cnt - LL; if (off < 0) off = 0;
        if (rank0 >= off) {
            int m = atomicAdd(&g_count, 1);
            g_src[m] = b * HH + h;
            g_dst[m] = (b * SS + (g - 1)) * LL + (rank0 - off);
        }
    }
    if (h < SS) {
        int cnt = (int)((tot >> (h * 16)) & 0xFFFF);
        int kept = (cnt == 0) ? 1 : (cnt < LL ? cnt : LL);
        g_kept[b * SS + h] = kept;
        g_emptyf[b * SS + h] = (cnt == 0) ? 1 : 0;
    }
}

// ---------------------------------------------------------------------------
// Output base init + mask
// ---------------------------------------------------------------------------
__global__ void k_base(const float* __restrict__ pos_emb, const float* __restrict__ seq_emb,
                       const float* __restrict__ empty_tok, float* __restrict__ out,
                       int write_mask) {
    int r = blockIdx.x;
    int slot = r & (LL - 1);
    int bg = r >> 8;
    int g = bg & (SS - 1);
    int kept = g_kept[bg];
    int tid = threadIdx.x;

    float4 val = make_float4(0.f, 0.f, 0.f, 0.f);
    if (slot < kept) {
        float4 a = ((const float4*)(pos_emb + (size_t)slot * DD))[tid];
        float4 q = ((const float4*)(seq_emb + (size_t)(g + 1) * DD))[tid];
        val.x = a.x + q.x; val.y = a.y + q.y; val.z = a.z + q.z; val.w = a.w + q.w;
        if (slot == 0 && g_emptyf[bg]) {
            float4 e = ((const float4*)(empty_tok + (size_t)g * DD))[tid];
            val.x += e.x; val.y += e.y; val.z += e.z; val.w += e.w;
        }
    }
    ((float4*)out)[(size_t)r * (DD / 4) + tid] = val;
    if (write_mask && tid == 0)
        out[STATES_ELEMS + r] = (slot < kept) ? 1.0f : 0.0f;
}

// ---------------------------------------------------------------------------
// Weight transpose [K,N] -> [N,K], fp16 output
// ---------------------------------------------------------------------------
__global__ void k_transpose(const float* __restrict__ W, __half* __restrict__ Wt, int K, int N) {
    __shared__ float t[32][33];
    int n0 = blockIdx.x * 32, k0 = blockIdx.y * 32;
    int tx = threadIdx.x, ty = threadIdx.y;   // 32 x 8
    #pragma unroll
    for (int j = 0; j < 32; j += 8)
        t[ty + j][tx] = W[(size_t)(k0 + ty + j) * N + n0 + tx];
    __syncthreads();
    #pragma unroll
    for (int j = 0; j < 32; j += 8)
        Wt[(size_t)(n0 + ty + j) * K + k0 + tx] = __float2half_rn(t[tx][ty + j]);
}

// ---------------------------------------------------------------------------
// Gather 5 embeddings + LayerNorm, store fp16 compact rows
// Each thread handles 5 float2 pairs (2560 = 256 threads * 2 * 5).
// ---------------------------------------------------------------------------
__global__ void k_gather_ln(const float* __restrict__ embed, const float* __restrict__ tg_emb,
                            const float* __restrict__ gamma, const float* __restrict__ beta,
                            const int* __restrict__ ht, const int* __restrict__ pt,
                            const int* __restrict__ at, const int* __restrict__ ct,
                            const int* __restrict__ tgap) {
    int m = blockIdx.x;
    if (m >= g_count) return;
    __shared__ const float* segs[5];
    __shared__ float s_mean, s_rstd;
    int tid = threadIdx.x;

    if (tid == 0) {
        int src = g_src[m];
        segs[0] = embed + (size_t)ht[src] * DD;
        segs[1] = embed + (size_t)pt[src] * DD;
        segs[2] = embed + (size_t)at[src] * DD;
        segs[3] = embed + (size_t)ct[src] * DD;
        int tg = tgap[src];
        tg = tg < 0 ? 0 : (tg > TGBB ? TGBB : tg);
        segs[4] = tg_emb + (size_t)tg * DD;
    }
    __syncthreads();

    float2 vals[5];
    float s = 0.f, ss = 0.f;
    #pragma unroll
    for (int k = 0; k < 5; k++) {
        int j = tid * 2 + k * 512;
        float2 v = *(const float2*)(segs[j >> 9] + (j & 511));
        vals[k] = v;
        s += v.x + v.y; ss += v.x * v.x + v.y * v.y;
    }
    #pragma unroll
    for (int o = 16; o > 0; o >>= 1) {
        s  += __shfl_down_sync(0xffffffffu, s,  o);
        ss += __shfl_down_sync(0xffffffffu, ss, o);
    }
    __shared__ float rs[8], rss[8];
    if ((tid & 31) == 0) { rs[tid >> 5] = s; rss[tid >> 5] = ss; }
    __syncthreads();
    if (tid == 0) {
        float S1 = 0.f, S2 = 0.f;
        #pragma unroll
        for (int w = 0; w < 8; w++) { S1 += rs[w]; S2 += rss[w]; }
        float mean = S1 * (1.0f / (float)KD1);
        float var = S2 * (1.0f / (float)KD1) - mean * mean;
        s_mean = mean;
        s_rstd = rsqrtf(var + 1e-5f);
    }
    __syncthreads();
    float mean = s_mean, rstd = s_rstd;
    size_t base = (size_t)m * KD1;
    #pragma unroll
    for (int k = 0; k < 5; k++) {
        int j = tid * 2 + k * 512;
        float gx = gamma[j], gy = gamma[j + 1];
        float bx = beta[j],  by = beta[j + 1];
        float x = (vals[k].x - mean) * rstd * gx + bx;
        float y = (vals[k].y - mean) * rstd * gy + by;
        *(half2*)&g_x[base + j] = __floats2half2_rn(x, y);
    }
}

// ---------------------------------------------------------------------------
// FP16 mma.sync GEMM: CTA tile 128(M) x 128(N), K-chunk 32, 4-stage cp.async.
// 8 warps (2x4), each 64x32 via 4x4 m16n8k16 tiles. Row pitch 40 halves (80B)
// -> all fragment LDS bank-conflict-free: bank = (20r + tig + c) % 32.
// MODE 0: g_h = fp16(silu(g_x @ w1 + b1))   K=2560, N=2048
// MODE 1: out[g_dst[m]] += g_h @ w2 + b2    K=2048, N=512
// ---------------------------------------------------------------------------
#define ROWP      40                        // halves per smem row (32 + 8 pad)
#define TILE_HLV  (128 * ROWP)              // halves per A or B tile
#define STG_BYTES (TILE_HLV * 2 * 2)        // A + B per stage = 20480
#define GSMEM_BYTES (4 * STG_BYTES)         // 81920

template <int MODE>
__global__ void __launch_bounds__(256, 2)
k_mma(const __half* __restrict__ Bt, const float* __restrict__ bias, float* __restrict__ out) {
    constexpr int K  = MODE ? ND1 : KD1;
    constexpr int NC = K / 32;

    const int count = g_count;
    const int m0 = blockIdx.y * 128;
    if (m0 >= count) return;
    const int n0 = blockIdx.x * 128;
    const __half* __restrict__ A = MODE ? g_h : g_x;

    extern __shared__ __align__(16) __half sm[];
    const uint32_t sb = smem_u32(sm);
    const int tid = threadIdx.x;
    const int wid = tid >> 5, lane = tid & 31;
    const int wm = wid & 1, wn = wid >> 1;     // 2 x 4 warp grid
    const int g = lane >> 2, tig = lane & 3;
    const int mclamp = count - 1;

    float acc[4][4][4];
    #pragma unroll
    for (int mt = 0; mt < 4; mt++)
        #pragma unroll
        for (int nt = 0; nt < 4; nt++)
            #pragma unroll
            for (int q = 0; q < 4; q++) acc[mt][nt][q] = 0.f;

    // per chunk: A 128 rows x 32 halves (512 x 16B tasks), B same
    auto load_chunk = [&](int c, int st) {
        int kc = c * 32;
        uint32_t aB = sb + st * STG_BYTES;
        uint32_t bB = aB + TILE_HLV * 2;
        {
            int id = tid;                       // tasks tid, tid+256
            #pragma unroll
            for (int j = 0; j < 2; j++) {
                int r = id >> 2, cc = id & 3;
                int gr = m0 + r; gr = gr > mclamp ? mclamp : gr;
                cpasync16(aB + r * (ROWP * 2) + cc * 16, A + (size_t)gr * K + kc + cc * 8);
                id += 256;
            }
        }
        {
            int id = tid;
            #pragma unroll
            for (int j = 0; j < 2; j++) {
                int r = id >> 2, cc = id & 3;
                cpasync16(bB + r * (ROWP * 2) + cc * 16, Bt + (size_t)(n0 + r) * K + kc + cc * 8);
                id += 256;
            }
        }
    };

    #pragma unroll
    for (int c = 0; c < 3; c++) { load_chunk(c, c); CP_COMMIT(); }

    for (int i = 0; i < NC; i++) {
        if (i + 3 < NC) load_chunk(i + 3, (i + 3) & 3);
        CP_COMMIT();
        CP_WAIT3();
        __syncthreads();

        const __half* aS = sm + (size_t)(i & 3) * (STG_BYTES / 2);
        const __half* bS = aS + TILE_HLV;

        #pragma unroll
        for (int ks = 0; ks < 2; ks++) {
            int kb = ks * 16 + tig * 2;
            uint32_t afr[4][4];
            uint32_t bfr[4][2];
            #pragma unroll
            for (int mt = 0; mt < 4; mt++) {
                int r = wm * 64 + mt * 16 + g;
                afr[mt][0] = *(const uint32_t*)(aS + r * ROWP + kb);
                afr[mt][1] = *(const uint32_t*)(aS + (r + 8) * ROWP + kb);
                afr[mt][2] = *(const uint32_t*)(aS + r * ROWP + kb + 8);
                afr[mt][3] = *(const uint32_t*)(aS + (r + 8) * ROWP + kb + 8);
            }
            #pragma unroll
            for (int nt = 0; nt < 4; nt++) {
                int r = wn * 32 + nt * 8 + g;
                bfr[nt][0] = *(const uint32_t*)(bS + r * ROWP + kb);
                bfr[nt][1] = *(const uint32_t*)(bS + r * ROWP + kb + 8);
            }
            #pragma unroll
            for (int mt = 0; mt < 4; mt++)
                #pragma unroll
                for (int nt = 0; nt < 4; nt++)
                    mma_f16(acc[mt][nt], afr[mt], bfr[nt]);
        }
        __syncthreads();
    }

    // ---- epilogue ----
    int dstA[4], dstB[4];
    bool vA[4], vB[4];
    #pragma unroll
    for (int mt = 0; mt < 4; mt++) {
        int r1 = m0 + wm * 64 + mt * 16 + g;
        int r2 = r1 + 8;
        vA[mt] = r1 < count;
        vB[mt] = r2 < count;
        if (MODE == 1) {
            dstA[mt] = vA[mt] ? g_dst[r1] : 0;
            dstB[mt] = vB[mt] ? g_dst[r2] : 0;
        } else {
            dstA[mt] = r1; dstB[mt] = r2;
        }
    }
    #pragma unroll
    for (int nt = 0; nt < 4; nt++) {
        int c = n0 + wn * 32 + nt * 8 + tig * 2;
        float bx = __ldg(&bias[c]), by = __ldg(&bias[c + 1]);
        #pragma unroll
        for (int mt = 0; mt < 4; mt++) {
            if (MODE == 0) {
                if (vA[mt]) {
                    float x = acc[mt][nt][0] + bx, y = acc[mt][nt][1] + by;
                    x = x / (1.0f + expf(-x)); y = y / (1.0f + expf(-y));
                    *(half2*)&g_h[(size_t)dstA[mt] * ND1 + c] = __floats2half2_rn(x, y);
                }
                if (vB[mt]) {
                    float x = acc[mt][nt][2] + bx, y = acc[mt][nt][3] + by;
                    x = x / (1.0f + expf(-x)); y = y / (1.0f + expf(-y));
                    *(half2*)&g_h[(size_t)dstB[mt] * ND1 + c] = __floats2half2_rn(x, y);
                }
            } else {
                if (vA[mt]) {
                    float2* p = (float2*)&out[(size_t)dstA[mt] * ND2 + c];
                    float2 o = *p;
                    o.x += acc[mt][nt][0] + bx; o.y += acc[mt][nt][1] + by;
                    *p = o;
                }
                if (vB[mt]) {
                    float2* p = (float2*)&out[(size_t)dstB[mt] * ND2 + c];
                    float2 o = *p;
                    o.x += acc[mt][nt][2] + bx; o.y += acc[mt][nt][3] + by;
                    *p = o;
                }
            }
        }
    }
}

// ---------------------------------------------------------------------------
extern "C" void kernel_launch(void* const* d_in, const int* in_sizes, int n_in,
                              void* d_out, int out_size) {
    const float* embed     = (const float*)d_in[0];
    const float* tg_emb    = (const float*)d_in[1];
    const float* seq_emb   = (const float*)d_in[2];
    const float* pos_emb   = (const float*)d_in[3];
    const float* gamma     = (const float*)d_in[4];
    const float* beta      = (const float*)d_in[5];
    const float* w1        = (const float*)d_in[6];
    const float* b1        = (const float*)d_in[7];
    const float* w2        = (const float*)d_in[8];
    const float* b2        = (const float*)d_in[9];
    const float* empty_tok = (const float*)d_in[10];
    const int*   ht        = (const int*)d_in[11];
    const int*   pt        = (const int*)d_in[12];
    const int*   at        = (const int*)d_in[13];
    const int*   ct        = (const int*)d_in[14];
    const int*   tgap      = (const int*)d_in[15];
    const int*   gids      = (const int*)d_in[16];
    const int*   lengths   = (const int*)d_in[17];
    float* out = (float*)d_out;

    int write_mask = ((size_t)out_size >= STATES_ELEMS + MASK_ELEMS) ? 1 : 0;

    __half* w1t_p; cudaGetSymbolAddress((void**)&w1t_p, g_w1t);
    __half* w2t_p; cudaGetSymbolAddress((void**)&w2t_p, g_w2t);

    cudaFuncSetAttribute(k_mma<0>, cudaFuncAttributeMaxDynamicSharedMemorySize, GSMEM_BYTES);
    cudaFuncSetAttribute(k_mma<1>, cudaFuncAttributeMaxDynamicSharedMemorySize, GSMEM_BYTES);

    k_zero<<<1, 1>>>();
    k_build<<<BB, HH>>>(gids, lengths);
    k_base<<<BB * SS * LL, 128>>>(pos_emb, seq_emb, empty_tok, out, write_mask);
    k_transpose<<<dim3(ND1 / 32, KD1 / 32), dim3(32, 8)>>>(w1, w1t_p, KD1, ND1);
    k_transpose<<<dim3(ND2 / 32, ND1 / 32), dim3(32, 8)>>>(w2, w2t_p, ND1, ND2);
    k_gather_ln<<<MAXM, 256>>>(embed, tg_emb, gamma, beta, ht, pt, at, ct, tgap);
    k_mma<0><<<dim3(ND1 / 128, MAXM / 128), 256, GSMEM_BYTES>>>(w1t_p, b1, nullptr);
    k_mma<1><<<dim3(ND2 / 128, MAXM / 128), 256, GSMEM_BYTES>>>(w2t_p, b2, out);
}

// round 5
// speedup vs baseline: 7.3563x; 1.2634x over previous
#include <cuda_runtime.h>
#include <cuda_fp16.h>
#include <math.h>
#include <stdint.h>

// Problem constants
#define BB   32
#define LL   256
#define SS   4
#define DD   512
#define HH   1024      // L*S
#define TGBB 128
#define KD1  2560      // 5*D
#define ND1  2048      // 4*D
#define ND2  512       // D
#define MAXM (BB*HH)   // 32768

#define STATES_ELEMS ((size_t)BB*SS*LL*DD)   // 16777216
#define MASK_ELEMS   ((size_t)BB*SS*LL)      // 32768

// Scratch (device globals; no runtime allocation)
__device__ __align__(128) __half g_x[(size_t)MAXM * KD1];   // LN'ed inputs, fp16 compact rows
__device__ __align__(128) __half g_h[(size_t)MAXM * ND1];   // hidden after silu, fp16
__device__ __align__(128) __half g_w1t[(size_t)ND1 * KD1];  // w1 transposed [N,K] fp16
__device__ __align__(128) __half g_w2t[(size_t)ND2 * ND1];  // w2 transposed [N,K] fp16
__device__ int   g_src[MAXM];
__device__ int   g_dst[MAXM];
__device__ int   g_count;
__device__ int   g_kept[BB * SS];
__device__ int   g_emptyf[BB * SS];

// ---------------------------------------------------------------------------
// Helpers
// ---------------------------------------------------------------------------
__device__ __forceinline__ uint32_t smem_u32(const void* p) {
    uint32_t a;
    asm("{ .reg .u64 t; cvta.to.shared.u64 t, %1; cvt.u32.u64 %0, t; }" : "=r"(a) : "l"(p));
    return a;
}
__device__ __forceinline__ void cpasync16(uint32_t dst, const void* src) {
    asm volatile("cp.async.cg.shared.global [%0], [%1], 16;\n" :: "r"(dst), "l"(src));
}
#define CP_COMMIT() asm volatile("cp.async.commit_group;\n" ::: "memory")
#define CP_WAIT2()  asm volatile("cp.async.wait_group 2;\n" ::: "memory")

__device__ __forceinline__ void mma_f16(float* c, const uint32_t* a, const uint32_t* b) {
    asm volatile(
        "mma.sync.aligned.m16n8k16.row.col.f32.f16.f16.f32 "
        "{%0,%1,%2,%3}, {%4,%5,%6,%7}, {%8,%9}, {%0,%1,%2,%3};"
        : "+f"(c[0]), "+f"(c[1]), "+f"(c[2]), "+f"(c[3])
        : "r"(a[0]), "r"(a[1]), "r"(a[2]), "r"(a[3]), "r"(b[0]), "r"(b[1]));
}
__device__ __forceinline__ void ldsm_x4(uint32_t* r, uint32_t addr) {
    asm volatile("ldmatrix.sync.aligned.m8n8.x4.shared.b16 {%0,%1,%2,%3}, [%4];"
        : "=r"(r[0]), "=r"(r[1]), "=r"(r[2]), "=r"(r[3]) : "r"(addr));
}

// ---------------------------------------------------------------------------
// Per-batch bucketization
// ---------------------------------------------------------------------------
__global__ void k_build(const int* __restrict__ gids, const int* __restrict__ lengths) {
    int b = blockIdx.x;
    int h = threadIdx.x;
    int len = lengths[b];
    int g = (h < len) ? gids[b * HH + h] : 0;

    unsigned long long v = (g > 0) ? (1ULL << ((g - 1) * 16)) : 0ULL;
    int lane = h & 31, wid = h >> 5;
    #pragma unroll
    for (int o = 1; o < 32; o <<= 1) {
        unsigned long long n = __shfl_up_sync(0xffffffffu, v, o);
        if (lane >= o) v += n;
    }
    __shared__ unsigned long long warpsum[32];
    if (lane == 31) warpsum[wid] = v;
    __syncthreads();
    if (wid == 0) {
        unsigned long long w = warpsum[lane];
        #pragma unroll
        for (int o = 1; o < 32; o <<= 1) {
            unsigned long long n = __shfl_up_sync(0xffffffffu, w, o);
            if (lane >= o) w += n;
        }
        warpsum[lane] = w;
    }
    __syncthreads();
    unsigned long long incl = v + (wid > 0 ? warpsum[wid - 1] : 0ULL);

    __shared__ unsigned long long s_total;
    if (h == HH - 1) s_total = incl;
    __syncthreads();
    unsigned long long tot = s_total;

    if (g > 0) {
        int rank0 = (int)((incl >> ((g - 1) * 16)) & 0xFFFF) - 1;
        int cnt   = (int)((tot  >> ((g - 1) * 16)) & 0xFFFF);
        int off = cnt - LL; if (off < 0) off = 0;
        if (rank0 >= off) {
            int m = atomicAdd(&g_count, 1);
            g_src[m] = b * HH + h;
            g_dst[m] = (b * SS + (g - 1)) * LL + (rank0 - off);
        }
    }
    if (h < SS) {
        int cnt = (int)((tot >> (h * 16)) & 0xFFFF);
        int kept = (cnt == 0) ? 1 : (cnt < LL ? cnt : LL);
        g_kept[b * SS + h] = kept;
        g_emptyf[b * SS + h] = (cnt == 0) ? 1 : 0;
    }
}

// ---------------------------------------------------------------------------
// Output base init + mask
// ---------------------------------------------------------------------------
__global__ void k_base(const float* __restrict__ pos_emb, const float* __restrict__ seq_emb,
                       const float* __restrict__ empty_tok, float* __restrict__ out,
                       int write_mask) {
    int r = blockIdx.x;
    int slot = r & (LL - 1);
    int bg = r >> 8;
    int g = bg & (SS - 1);
    int kept = g_kept[bg];
    int tid = threadIdx.x;

    float4 val = make_float4(0.f, 0.f, 0.f, 0.f);
    if (slot < kept) {
        float4 a = ((const float4*)(pos_emb + (size_t)slot * DD))[tid];
        float4 q = ((const float4*)(seq_emb + (size_t)(g + 1) * DD))[tid];
        val.x = a.x + q.x; val.y = a.y + q.y; val.z = a.z + q.z; val.w = a.w + q.w;
        if (slot == 0 && g_emptyf[bg]) {
            float4 e = ((const float4*)(empty_tok + (size_t)g * DD))[tid];
            val.x += e.x; val.y += e.y; val.z += e.z; val.w += e.w;
        }
    }
    ((float4*)out)[(size_t)r * (DD / 4) + tid] = val;
    if (write_mask && tid == 0)
        out[STATES_ELEMS + r] = (slot < kept) ? 1.0f : 0.0f;
}

// ---------------------------------------------------------------------------
// Weight transpose [K,N] -> [N,K], fp16 output. Also resets g_count (first block).
// ---------------------------------------------------------------------------
__global__ void k_transpose(const float* __restrict__ W, __half* __restrict__ Wt, int K, int N) {
    if (blockIdx.x == 0 && blockIdx.y == 0 && threadIdx.x == 0 && threadIdx.y == 0)
        g_count = 0;
    __shared__ float t[32][33];
    int n0 = blockIdx.x * 32, k0 = blockIdx.y * 32;
    int tx = threadIdx.x, ty = threadIdx.y;   // 32 x 8
    #pragma unroll
    for (int j = 0; j < 32; j += 8)
        t[ty + j][tx] = W[(size_t)(k0 + ty + j) * N + n0 + tx];
    __syncthreads();
    #pragma unroll
    for (int j = 0; j < 32; j += 8)
        Wt[(size_t)(n0 + ty + j) * K + k0 + tx] = __float2half_rn(t[tx][ty + j]);
}

// ---------------------------------------------------------------------------
// Gather 5 embeddings + LayerNorm, store fp16 compact rows
// ---------------------------------------------------------------------------
__global__ void k_gather_ln(const float* __restrict__ embed, const float* __restrict__ tg_emb,
                            const float* __restrict__ gamma, const float* __restrict__ beta,
                            const int* __restrict__ ht, const int* __restrict__ pt,
                            const int* __restrict__ at, const int* __restrict__ ct,
                            const int* __restrict__ tgap) {
    int m = blockIdx.x;
    if (m >= g_count) return;
    __shared__ const float* segs[5];
    __shared__ float s_mean, s_rstd;
    int tid = threadIdx.x;

    if (tid == 0) {
        int src = g_src[m];
        segs[0] = embed + (size_t)ht[src] * DD;
        segs[1] = embed + (size_t)pt[src] * DD;
        segs[2] = embed + (size_t)at[src] * DD;
        segs[3] = embed + (size_t)ct[src] * DD;
        int tg = tgap[src];
        tg = tg < 0 ? 0 : (tg > TGBB ? TGBB : tg);
        segs[4] = tg_emb + (size_t)tg * DD;
    }
    __syncthreads();

    float2 vals[5];
    float s = 0.f, ss = 0.f;
    #pragma unroll
    for (int k = 0; k < 5; k++) {
        int j = tid * 2 + k * 512;
        float2 v = *(const float2*)(segs[j >> 9] + (j & 511));
        vals[k] = v;
        s += v.x + v.y; ss += v.x * v.x + v.y * v.y;
    }
    #pragma unroll
    for (int o = 16; o > 0; o >>= 1) {
        s  += __shfl_down_sync(0xffffffffu, s,  o);
        ss += __shfl_down_sync(0xffffffffu, ss, o);
    }
    __shared__ float rs[8], rss[8];
    if ((tid & 31) == 0) { rs[tid >> 5] = s; rss[tid >> 5] = ss; }
    __syncthreads();
    if (tid == 0) {
        float S1 = 0.f, S2 = 0.f;
        #pragma unroll
        for (int w = 0; w < 8; w++) { S1 += rs[w]; S2 += rss[w]; }
        float mean = S1 * (1.0f / (float)KD1);
        float var = S2 * (1.0f / (float)KD1) - mean * mean;
        s_mean = mean;
        s_rstd = rsqrtf(var + 1e-5f);
    }
    __syncthreads();
    float mean = s_mean, rstd = s_rstd;
    size_t base = (size_t)m * KD1;
    #pragma unroll
    for (int k = 0; k < 5; k++) {
        int j = tid * 2 + k * 512;
        float gx = gamma[j], gy = gamma[j + 1];
        float bx = beta[j],  by = beta[j + 1];
        float x = (vals[k].x - mean) * rstd * gx + bx;
        float y = (vals[k].y - mean) * rstd * gy + by;
        *(half2*)&g_x[base + j] = __floats2half2_rn(x, y);
    }
}

// ---------------------------------------------------------------------------
// FP16 mma.sync GEMM: CTA tile 128(M) x 128(N), K-chunk 64, 3-stage cp.async.
// 8 warps (2x4 grid), each 64x32 via 4x4 m16n8k16 tiles, ldmatrix.x4 fragment
// loads. Row pitch 72 halves (144B = 9x16B, 9 coprime 8) -> conflict-free.
// MODE 0: g_h = fp16(silu(g_x @ w1 + b1))   K=2560, N=2048
// MODE 1: out[g_dst[m]] += g_h @ w2 + b2    K=2048, N=512
// ---------------------------------------------------------------------------
#define ROWP      72                        // halves per smem row (64 + 8 pad)
#define ROWB      (ROWP * 2)                // 144 bytes
#define TILE_B    (128 * ROWB)              // 18432 bytes per A or B tile
#define STG_BYTES (TILE_B * 2)              // 36864
#define NSTG      3
#define GSMEM_BYTES (NSTG * STG_BYTES)      // 110592

template <int MODE>
__global__ void __launch_bounds__(256, 2)
k_mma(const __half* __restrict__ Bt, const float* __restrict__ bias, float* __restrict__ out) {
    constexpr int K  = MODE ? ND1 : KD1;
    constexpr int NC = K / 64;

    const int count = g_count;
    const int m0 = blockIdx.y * 128;
    if (m0 >= count) return;
    const int n0 = blockIdx.x * 128;
    const __half* __restrict__ A = MODE ? g_h : g_x;

    extern __shared__ __align__(16) char smc[];
    const uint32_t sb = smem_u32(smc);
    const int tid = threadIdx.x;
    const int wid = tid >> 5, lane = tid & 31;
    const int wm = wid & 1, wn = wid >> 1;     // 2 x 4 warp grid
    const int g = lane >> 2, tig = lane & 3;
    const int mclamp = count - 1;

    // ldmatrix lane-derived byte offsets (within a tile, before ks/tile adds)
    const uint32_t aLane = (uint32_t)(lane & 15) * ROWB + ((lane >> 4) << 3) * 2;
    const uint32_t bLane = (uint32_t)(((lane >> 4) << 3) + (lane & 7)) * ROWB
                         + (((lane >> 3) & 1) << 3) * 2;

    float acc[4][4][4];
    #pragma unroll
    for (int mt = 0; mt < 4; mt++)
        #pragma unroll
        for (int nt = 0; nt < 4; nt++)
            #pragma unroll
            for (int q = 0; q < 4; q++) acc[mt][nt][q] = 0.f;

    // per chunk: A 128 rows x 64 halves (1024 x 16B tasks), B same
    auto load_chunk = [&](int c, int st) {
        int kc = c * 64;
        uint32_t aB = sb + st * STG_BYTES;
        uint32_t bB = aB + TILE_B;
        int id = tid;
        #pragma unroll
        for (int j = 0; j < 4; j++) {
            int r = id >> 3, cc = id & 7;
            int gr = m0 + r; gr = gr > mclamp ? mclamp : gr;
            cpasync16(aB + r * ROWB + cc * 16, A + (size_t)gr * K + kc + cc * 8);
            id += 256;
        }
        id = tid;
        #pragma unroll
        for (int j = 0; j < 4; j++) {
            int r = id >> 3, cc = id & 7;
            cpasync16(bB + r * ROWB + cc * 16, Bt + (size_t)(n0 + r) * K + kc + cc * 8);
            id += 256;
        }
    };

    #pragma unroll
    for (int c = 0; c < NSTG; c++) { load_chunk(c, c); CP_COMMIT(); }

    int stage = 0;
    for (int i = 0; i < NC; i++) {
        CP_WAIT2();
        __syncthreads();

        uint32_t aS = sb + stage * STG_BYTES;
        uint32_t bS = aS + TILE_B;

        #pragma unroll
        for (int ks = 0; ks < 4; ks++) {
            uint32_t kOff = ks * 32;           // 16 halves = 32 bytes
            uint32_t afr[4][4];
            uint32_t bfr[2][4];
            #pragma unroll
            for (int mt = 0; mt < 4; mt++)
                ldsm_x4(afr[mt], aS + (uint32_t)(wm * 64 + mt * 16) * ROWB + aLane + kOff);
            #pragma unroll
            for (int p = 0; p < 2; p++)
                ldsm_x4(bfr[p], bS + (uint32_t)(wn * 32 + p * 16) * ROWB + bLane + kOff);
            #pragma unroll
            for (int mt = 0; mt < 4; mt++) {
                #pragma unroll
                for (int p = 0; p < 2; p++) {
                    mma_f16(acc[mt][2 * p],     afr[mt], &bfr[p][0]);
                    mma_f16(acc[mt][2 * p + 1], afr[mt], &bfr[p][2]);
                }
            }
        }
        __syncthreads();
        if (i + NSTG < NC) load_chunk(i + NSTG, stage);
        CP_COMMIT();
        stage = (stage == NSTG - 1) ? 0 : stage + 1;
    }

    // ---- epilogue ----
    int dstA[4], dstB[4];
    bool vA[4], vB[4];
    #pragma unroll
    for (int mt = 0; mt < 4; mt++) {
        int r1 = m0 + wm * 64 + mt * 16 + g;
        int r2 = r1 + 8;
        vA[mt] = r1 < count;
        vB[mt] = r2 < count;
        if (MODE == 1) {
            dstA[mt] = vA[mt] ? g_dst[r1] : 0;
            dstB[mt] = vB[mt] ? g_dst[r2] : 0;
        } else {
            dstA[mt] = r1; dstB[mt] = r2;
        }
    }
    #pragma unroll
    for (int nt = 0; nt < 4; nt++) {
        int c = n0 + wn * 32 + nt * 8 + tig * 2;
        float bx = __ldg(&bias[c]), by = __ldg(&bias[c + 1]);
        #pragma unroll
        for (int mt = 0; mt < 4; mt++) {
            if (MODE == 0) {
                if (vA[mt]) {
                    float x = acc[mt][nt][0] + bx, y = acc[mt][nt][1] + by;
                    x = x / (1.0f + expf(-x)); y = y / (1.0f + expf(-y));
                    *(half2*)&g_h[(size_t)dstA[mt] * ND1 + c] = __floats2half2_rn(x, y);
                }
                if (vB[mt]) {
                    float x = acc[mt][nt][2] + bx, y = acc[mt][nt][3] + by;
                    x = x / (1.0f + expf(-x)); y = y / (1.0f + expf(-y));
                    *(half2*)&g_h[(size_t)dstB[mt] * ND1 + c] = __floats2half2_rn(x, y);
                }
            } else {
                if (vA[mt]) {
                    float2* p = (float2*)&out[(size_t)dstA[mt] * ND2 + c];
                    float2 o = *p;
                    o.x += acc[mt][nt][0] + bx; o.y += acc[mt][nt][1] + by;
                    *p = o;
                }
                if (vB[mt]) {
                    float2* p = (float2*)&out[(size_t)dstB[mt] * ND2 + c];
                    float2 o = *p;
                    o.x += acc[mt][nt][2] + bx; o.y += acc[mt][nt][3] + by;
                    *p = o;
                }
            }
        }
    }
}

// ---------------------------------------------------------------------------
extern "C" void kernel_launch(void* const* d_in, const int* in_sizes, int n_in,
                              void* d_out, int out_size) {
    const float* embed     = (const float*)d_in[0];
    const float* tg_emb    = (const float*)d_in[1];
    const float* seq_emb   = (const float*)d_in[2];
    const float* pos_emb   = (const float*)d_in[3];
    const float* gamma     = (const float*)d_in[4];
    const float* beta      = (const float*)d_in[5];
    const float* w1        = (const float*)d_in[6];
    const float* b1        = (const float*)d_in[7];
    const float* w2        = (const float*)d_in[8];
    const float* b2        = (const float*)d_in[9];
    const float* empty_tok = (const float*)d_in[10];
    const int*   ht        = (const int*)d_in[11];
    const int*   pt        = (const int*)d_in[12];
    const int*   at        = (const int*)d_in[13];
    const int*   ct        = (const int*)d_in[14];
    const int*   tgap      = (const int*)d_in[15];
    const int*   gids      = (const int*)d_in[16];
    const int*   lengths   = (const int*)d_in[17];
    float* out = (float*)d_out;

    int write_mask = ((size_t)out_size >= STATES_ELEMS + MASK_ELEMS) ? 1 : 0;

    __half* w1t_p; cudaGetSymbolAddress((void**)&w1t_p, g_w1t);
    __half* w2t_p; cudaGetSymbolAddress((void**)&w2t_p, g_w2t);

    cudaFuncSetAttribute(k_mma<0>, cudaFuncAttributeMaxDynamicSharedMemorySize, GSMEM_BYTES);
    cudaFuncSetAttribute(k_mma<1>, cudaFuncAttributeMaxDynamicSharedMemorySize, GSMEM_BYTES);

    k_transpose<<<dim3(ND1 / 32, KD1 / 32), dim3(32, 8)>>>(w1, w1t_p, KD1, ND1);   // also resets g_count
    k_transpose<<<dim3(ND2 / 32, ND1 / 32), dim3(32, 8)>>>(w2, w2t_p, ND1, ND2);
    k_build<<<BB, HH>>>(gids, lengths);
    k_base<<<BB * SS * LL, 128>>>(pos_emb, seq_emb, empty_tok, out, write_mask);
    k_gather_ln<<<MAXM, 256>>>(embed, tg_emb, gamma, beta, ht, pt, at, ct, tgap);
    k_mma<0><<<dim3(ND1 / 128, MAXM / 128), 256, GSMEM_BYTES>>>(w1t_p, b1, nullptr);
    k_mma<1><<<dim3(ND2 / 128, MAXM / 128), 256, GSMEM_BYTES>>>(w2t_p, b2, out);
}

// round 6
// speedup vs baseline: 7.7958x; 1.0597x over previous
#include <cuda_runtime.h>
#include <cuda_fp16.h>
#include <math.h>
#include <stdint.h>

// Problem constants
#define BB   32
#define LL   256
#define SS   4
#define DD   512
#define HH   1024      // L*S
#define TGBB 128
#define KD1  2560      // 5*D
#define ND1  2048      // 4*D
#define ND2  512       // D
#define MAXM (BB*HH)   // 32768

#define STATES_ELEMS ((size_t)BB*SS*LL*DD)   // 16777216
#define MASK_ELEMS   ((size_t)BB*SS*LL)      // 32768

// Scratch (device globals; no runtime allocation)
__device__ __align__(128) __half g_x[(size_t)MAXM * KD1];
__device__ __align__(128) __half g_h[(size_t)MAXM * ND1];
__device__ __align__(128) __half g_w1t[(size_t)ND1 * KD1];
__device__ __align__(128) __half g_w2t[(size_t)ND2 * ND1];
__device__ int   g_src[MAXM];
__device__ int   g_dst[MAXM];
__device__ int   g_count;
__device__ int   g_kept[BB * SS];
__device__ int   g_emptyf[BB * SS];

// ---------------------------------------------------------------------------
// Helpers
// ---------------------------------------------------------------------------
__device__ __forceinline__ uint32_t smem_u32(const void* p) {
    uint32_t a;
    asm("{ .reg .u64 t; cvta.to.shared.u64 t, %1; cvt.u32.u64 %0, t; }" : "=r"(a) : "l"(p));
    return a;
}
__device__ __forceinline__ void cpasync16(uint32_t dst, const void* src) {
    asm volatile("cp.async.cg.shared.global [%0], [%1], 16;\n" :: "r"(dst), "l"(src));
}
#define CP_COMMIT() asm volatile("cp.async.commit_group;\n" ::: "memory")
#define CP_WAIT2()  asm volatile("cp.async.wait_group 2;\n" ::: "memory")

__device__ __forceinline__ void mma_f16(float* c, const uint32_t* a, const uint32_t* b) {
    asm volatile(
        "mma.sync.aligned.m16n8k16.row.col.f32.f16.f16.f32 "
        "{%0,%1,%2,%3}, {%4,%5,%6,%7}, {%8,%9}, {%0,%1,%2,%3};"
        : "+f"(c[0]), "+f"(c[1]), "+f"(c[2]), "+f"(c[3])
        : "r"(a[0]), "r"(a[1]), "r"(a[2]), "r"(a[3]), "r"(b[0]), "r"(b[1]));
}
__device__ __forceinline__ void ldsm_x4(uint32_t* r, uint32_t addr) {
    asm volatile("ldmatrix.sync.aligned.m8n8.x4.shared.b16 {%0,%1,%2,%3}, [%4];"
        : "=r"(r[0]), "=r"(r[1]), "=r"(r[2]), "=r"(r[3]) : "r"(addr));
}

// ---------------------------------------------------------------------------
// Per-batch bucketization
// ---------------------------------------------------------------------------
__global__ void k_build(const int* __restrict__ gids, const int* __restrict__ lengths) {
    int b = blockIdx.x;
    int h = threadIdx.x;
    int len = lengths[b];
    int g = (h < len) ? gids[b * HH + h] : 0;

    unsigned long long v = (g > 0) ? (1ULL << ((g - 1) * 16)) : 0ULL;
    int lane = h & 31, wid = h >> 5;
    #pragma unroll
    for (int o = 1; o < 32; o <<= 1) {
        unsigned long long n = __shfl_up_sync(0xffffffffu, v, o);
        if (lane >= o) v += n;
    }
    __shared__ unsigned long long warpsum[32];
    if (lane == 31) warpsum[wid] = v;
    __syncthreads();
    if (wid == 0) {
        unsigned long long w = warpsum[lane];
        #pragma unroll
        for (int o = 1; o < 32; o <<= 1) {
            unsigned long long n = __shfl_up_sync(0xffffffffu, w, o);
            if (lane >= o) w += n;
        }
        warpsum[lane] = w;
    }
    __syncthreads();
    unsigned long long incl = v + (wid > 0 ? warpsum[wid - 1] : 0ULL);

    __shared__ unsigned long long s_total;
    if (h == HH - 1) s_total = incl;
    __syncthreads();
    unsigned long long tot = s_total;

    if (g > 0) {
        int rank0 = (int)((incl >> ((g - 1) * 16)) & 0xFFFF) - 1;
        int cnt   = (int)((tot  >> ((g - 1) * 16)) & 0xFFFF);
        int off = cnt - LL; if (off < 0) off = 0;
        if (rank0 >= off) {
            int m = atomicAdd(&g_count, 1);
            g_src[m] = b * HH + h;
            g_dst[m] = (b * SS + (g - 1)) * LL + (rank0 - off);
        }
    }
    if (h < SS) {
        int cnt = (int)((tot >> (h * 16)) & 0xFFFF);
        int kept = (cnt == 0) ? 1 : (cnt < LL ? cnt : LL);
        g_kept[b * SS + h] = kept;
        g_emptyf[b * SS + h] = (cnt == 0) ? 1 : 0;
    }
}

// ---------------------------------------------------------------------------
// Output base init + mask: 128 threads, 4 consecutive rows per block
// ---------------------------------------------------------------------------
__global__ void k_base(const float* __restrict__ pos_emb, const float* __restrict__ seq_emb,
                       const float* __restrict__ empty_tok, float* __restrict__ out,
                       int write_mask) {
    int tid = threadIdx.x;
    int r0 = blockIdx.x * 4;
    #pragma unroll
    for (int q = 0; q < 4; q++) {
        int r = r0 + q;
        int slot = r & (LL - 1);
        int bg = r >> 8;
        int g = bg & (SS - 1);
        int kept = g_kept[bg];

        float4 val = make_float4(0.f, 0.f, 0.f, 0.f);
        if (slot < kept) {
            float4 a = ((const float4*)(pos_emb + (size_t)slot * DD))[tid];
            float4 qv = ((const float4*)(seq_emb + (size_t)(g + 1) * DD))[tid];
            val.x = a.x + qv.x; val.y = a.y + qv.y; val.z = a.z + qv.z; val.w = a.w + qv.w;
            if (slot == 0 && g_emptyf[bg]) {
                float4 e = ((const float4*)(empty_tok + (size_t)g * DD))[tid];
                val.x += e.x; val.y += e.y; val.z += e.z; val.w += e.w;
            }
        }
        ((float4*)out)[(size_t)r * (DD / 4) + tid] = val;
        if (write_mask && tid == 0)
            out[STATES_ELEMS + r] = (slot < kept) ? 1.0f : 0.0f;
    }
}

// ---------------------------------------------------------------------------
// Weight transpose [K,N] -> [N,K], fp16 output
// ---------------------------------------------------------------------------
__global__ void k_transpose(const float* __restrict__ W, __half* __restrict__ Wt, int K, int N) {
    __shared__ float t[32][33];
    int n0 = blockIdx.x * 32, k0 = blockIdx.y * 32;
    int tx = threadIdx.x, ty = threadIdx.y;   // 32 x 8
    #pragma unroll
    for (int j = 0; j < 32; j += 8)
        t[ty + j][tx] = W[(size_t)(k0 + ty + j) * N + n0 + tx];
    __syncthreads();
    #pragma unroll
    for (int j = 0; j < 32; j += 8)
        Wt[(size_t)(n0 + ty + j) * K + k0 + tx] = __float2half_rn(t[tx][ty + j]);
}

// ---------------------------------------------------------------------------
// Gather 5 embeddings + LayerNorm: 128 threads, 5 float4 per thread.
// Thread t covers floats [4t, 4t+4) of each of the 5 segments (coalesced).
// ---------------------------------------------------------------------------
__global__ void k_gather_ln(const float* __restrict__ embed, const float* __restrict__ tg_emb,
                            const float* __restrict__ gamma, const float* __restrict__ beta,
                            const int* __restrict__ ht, const int* __restrict__ pt,
                            const int* __restrict__ at, const int* __restrict__ ct,
                            const int* __restrict__ tgap) {
    int m = blockIdx.x;
    if (m >= g_count) return;
    __shared__ const float* segs[5];
    __shared__ float s_mean, s_rstd;
    __shared__ float rs[4], rss[4];
    int tid = threadIdx.x;   // 128

    if (tid == 0) {
        int src = g_src[m];
        segs[0] = embed + (size_t)ht[src] * DD;
        segs[1] = embed + (size_t)pt[src] * DD;
        segs[2] = embed + (size_t)at[src] * DD;
        segs[3] = embed + (size_t)ct[src] * DD;
        int tg = tgap[src];
        tg = tg < 0 ? 0 : (tg > TGBB ? TGBB : tg);
        segs[4] = tg_emb + (size_t)tg * DD;
    }
    __syncthreads();

    float4 v[5];
    float s = 0.f, ss = 0.f;
    #pragma unroll
    for (int k = 0; k < 5; k++) {
        v[k] = *(const float4*)(segs[k] + tid * 4);
        s  += v[k].x + v[k].y + v[k].z + v[k].w;
        ss += v[k].x * v[k].x + v[k].y * v[k].y + v[k].z * v[k].z + v[k].w * v[k].w;
    }
    #pragma unroll
    for (int o = 16; o > 0; o >>= 1) {
        s  += __shfl_down_sync(0xffffffffu, s,  o);
        ss += __shfl_down_sync(0xffffffffu, ss, o);
    }
    if ((tid & 31) == 0) { rs[tid >> 5] = s; rss[tid >> 5] = ss; }
    __syncthreads();
    if (tid == 0) {
        float S1 = rs[0] + rs[1] + rs[2] + rs[3];
        float S2 = rss[0] + rss[1] + rss[2] + rss[3];
        float mean = S1 * (1.0f / (float)KD1);
        float var = S2 * (1.0f / (float)KD1) - mean * mean;
        s_mean = mean;
        s_rstd = rsqrtf(var + 1e-5f);
    }
    __syncthreads();
    float mean = s_mean, rstd = s_rstd;
    size_t base = (size_t)m * KD1;
    #pragma unroll
    for (int k = 0; k < 5; k++) {
        int j = k * 512 + tid * 4;
        float4 gm = *(const float4*)(gamma + j);
        float4 bt = *(const float4*)(beta + j);
        float x0 = (v[k].x - mean) * rstd * gm.x + bt.x;
        float x1 = (v[k].y - mean) * rstd * gm.y + bt.y;
        float x2 = (v[k].z - mean) * rstd * gm.z + bt.z;
        float x3 = (v[k].w - mean) * rstd * gm.w + bt.w;
        half2 h0 = __floats2half2_rn(x0, x1);
        half2 h1 = __floats2half2_rn(x2, x3);
        *(uint2*)&g_x[base + j] = make_uint2(*(uint32_t*)&h0, *(uint32_t*)&h1);
    }
}

// ---------------------------------------------------------------------------
// FP16 mma.sync GEMM: CTA tile 128x128, K-chunk 64, 3-stage cp.async,
// ldmatrix.x4 fragments, row pitch 72 halves (conflict-free).
// MODE 0: g_h = fp16(silu(g_x @ w1 + b1))   K=2560, N=2048
// MODE 1: out[g_dst[m]] += g_h @ w2 + b2    K=2048, N=512
// ---------------------------------------------------------------------------
#define ROWP      72
#define ROWB      (ROWP * 2)                // 144 bytes
#define TILE_B    (128 * ROWB)              // 18432
#define STG_BYTES (TILE_B * 2)              // 36864
#define NSTG      3
#define GSMEM_BYTES (NSTG * STG_BYTES)      // 110592

template <int MODE>
__global__ void __launch_bounds__(256, 2)
k_mma(const __half* __restrict__ Bt, const float* __restrict__ bias, float* __restrict__ out) {
    constexpr int K  = MODE ? ND1 : KD1;
    constexpr int NC = K / 64;

    const int count = g_count;
    const int m0 = blockIdx.y * 128;
    if (m0 >= count) return;
    const int n0 = blockIdx.x * 128;
    const __half* __restrict__ A = MODE ? g_h : g_x;

    extern __shared__ __align__(16) char smc[];
    const uint32_t sb = smem_u32(smc);
    const int tid = threadIdx.x;
    const int wid = tid >> 5, lane = tid & 31;
    const int wm = wid & 1, wn = wid >> 1;
    const int g = lane >> 2, tig = lane & 3;
    const int mclamp = count - 1;

    const uint32_t aLane = (uint32_t)(lane & 15) * ROWB + ((lane >> 4) << 3) * 2;
    const uint32_t bLane = (uint32_t)(((lane >> 4) << 3) + (lane & 7)) * ROWB
                         + (((lane >> 3) & 1) << 3) * 2;

    float acc[4][4][4];
    #pragma unroll
    for (int mt = 0; mt < 4; mt++)
        #pragma unroll
        for (int nt = 0; nt < 4; nt++)
            #pragma unroll
            for (int q = 0; q < 4; q++) acc[mt][nt][q] = 0.f;

    auto load_chunk = [&](int c, int st) {
        int kc = c * 64;
        uint32_t aB = sb + st * STG_BYTES;
        uint32_t bB = aB + TILE_B;
        int id = tid;
        #pragma unroll
        for (int j = 0; j < 4; j++) {
            int r = id >> 3, cc = id & 7;
            int gr = m0 + r; gr = gr > mclamp ? mclamp : gr;
            cpasync16(aB + r * ROWB + cc * 16, A + (size_t)gr * K + kc + cc * 8);
            id += 256;
        }
        id = tid;
        #pragma unroll
        for (int j = 0; j < 4; j++) {
            int r = id >> 3, cc = id & 7;
            cpasync16(bB + r * ROWB + cc * 16, Bt + (size_t)(n0 + r) * K + kc + cc * 8);
            id += 256;
        }
    };

    #pragma unroll
    for (int c = 0; c < NSTG; c++) { load_chunk(c, c); CP_COMMIT(); }

    int stage = 0;
    for (int i = 0; i < NC; i++) {
        CP_WAIT2();
        __syncthreads();

        uint32_t aS = sb + stage * STG_BYTES;
        uint32_t bS = aS + TILE_B;

        #pragma unroll
        for (int ks = 0; ks < 4; ks++) {
            uint32_t kOff = ks * 32;
            uint32_t afr[4][4];
            uint32_t bfr[2][4];
            #pragma unroll
            for (int mt = 0; mt < 4; mt++)
                ldsm_x4(afr[mt], aS + (uint32_t)(wm * 64 + mt * 16) * ROWB + aLane + kOff);
            #pragma unroll
            for (int p = 0; p < 2; p++)
                ldsm_x4(bfr[p], bS + (uint32_t)(wn * 32 + p * 16) * ROWB + bLane + kOff);
            #pragma unroll
            for (int mt = 0; mt < 4; mt++) {
                #pragma unroll
                for (int p = 0; p < 2; p++) {
                    mma_f16(acc[mt][2 * p],     afr[mt], &bfr[p][0]);
                    mma_f16(acc[mt][2 * p + 1], afr[mt], &bfr[p][2]);
                }
            }
        }
        __syncthreads();
        if (i + NSTG < NC) load_chunk(i + NSTG, stage);
        CP_COMMIT();
        stage = (stage == NSTG - 1) ? 0 : stage + 1;
    }

    // ---- epilogue ----
    int dstA[4], dstB[4];
    bool vA[4], vB[4];
    #pragma unroll
    for (int mt = 0; mt < 4; mt++) {
        int r1 = m0 + wm * 64 + mt * 16 + g;
        int r2 = r1 + 8;
        vA[mt] = r1 < count;
        vB[mt] = r2 < count;
        if (MODE == 1) {
            dstA[mt] = vA[mt] ? g_dst[r1] : 0;
            dstB[mt] = vB[mt] ? g_dst[r2] : 0;
        } else {
            dstA[mt] = r1; dstB[mt] = r2;
        }
    }
    #pragma unroll
    for (int nt = 0; nt < 4; nt++) {
        int c = n0 + wn * 32 + nt * 8 + tig * 2;
        float bx = __ldg(&bias[c]), by = __ldg(&bias[c + 1]);
        #pragma unroll
        for (int mt = 0; mt < 4; mt++) {
            if (MODE == 0) {
                if (vA[mt]) {
                    float x = acc[mt][nt][0] + bx, y = acc[mt][nt][1] + by;
                    x = x / (1.0f + expf(-x)); y = y / (1.0f + expf(-y));
                    *(half2*)&g_h[(size_t)dstA[mt] * ND1 + c] = __floats2half2_rn(x, y);
                }
                if (vB[mt]) {
                    float x = acc[mt][nt][2] + bx, y = acc[mt][nt][3] + by;
                    x = x / (1.0f + expf(-x)); y = y / (1.0f + expf(-y));
                    *(half2*)&g_h[(size_t)dstB[mt] * ND1 + c] = __floats2half2_rn(x, y);
                }
            } else {
                if (vA[mt]) {
                    float2* p = (float2*)&out[(size_t)dstA[mt] * ND2 + c];
                    float2 o = *p;
                    o.x += acc[mt][nt][0] + bx; o.y += acc[mt][nt][1] + by;
                    *p = o;
                }
                if (vB[mt]) {
                    float2* p = (float2*)&out[(size_t)dstB[mt] * ND2 + c];
                    float2 o = *p;
                    o.x += acc[mt][nt][2] + bx; o.y += acc[mt][nt][3] + by;
                    *p = o;
                }
            }
        }
    }
}

// ---------------------------------------------------------------------------
extern "C" void kernel_launch(void* const* d_in, const int* in_sizes, int n_in,
                              void* d_out, int out_size) {
    const float* embed     = (const float*)d_in[0];
    const float* tg_emb    = (const float*)d_in[1];
    const float* seq_emb   = (const float*)d_in[2];
    const float* pos_emb   = (const float*)d_in[3];
    const float* gamma     = (const float*)d_in[4];
    const float* beta      = (const float*)d_in[5];
    const float* w1        = (const float*)d_in[6];
    const float* b1        = (const float*)d_in[7];
    const float* w2        = (const float*)d_in[8];
    const float* b2        = (const float*)d_in[9];
    const float* empty_tok = (const float*)d_in[10];
    const int*   ht        = (const int*)d_in[11];
    const int*   pt        = (const int*)d_in[12];
    const int*   at        = (const int*)d_in[13];
    const int*   ct        = (const int*)d_in[14];
    const int*   tgap      = (const int*)d_in[15];
    const int*   gids      = (const int*)d_in[16];
    const int*   lengths   = (const int*)d_in[17];
    float* out = (float*)d_out;

    int write_mask = ((size_t)out_size >= STATES_ELEMS + MASK_ELEMS) ? 1 : 0;

    __half* w1t_p; cudaGetSymbolAddress((void**)&w1t_p, g_w1t);
    __half* w2t_p; cudaGetSymbolAddress((void**)&w2t_p, g_w2t);
    int* cnt_p;    cudaGetSymbolAddress((void**)&cnt_p, g_count);

    static cudaStream_t s1 = nullptr;
    static cudaEvent_t evFork = nullptr, evBuild = nullptr, evT1 = nullptr, evSide = nullptr;
    if (!s1) {
        cudaStreamCreateWithFlags(&s1, cudaStreamNonBlocking);
        cudaEventCreateWithFlags(&evFork,  cudaEventDisableTiming);
        cudaEventCreateWithFlags(&evBuild, cudaEventDisableTiming);
        cudaEventCreateWithFlags(&evT1,    cudaEventDisableTiming);
        cudaEventCreateWithFlags(&evSide,  cudaEventDisableTiming);
    }

    cudaFuncSetAttribute(k_mma<0>, cudaFuncAttributeMaxDynamicSharedMemorySize, GSMEM_BYTES);
    cudaFuncSetAttribute(k_mma<1>, cudaFuncAttributeMaxDynamicSharedMemorySize, GSMEM_BYTES);

    // main stream (0): zero count -> build -> gather_ln -> mma0 -> mma1
    // side stream (s1): transposes + base, overlapped; joined before the GEMM that needs them.
    cudaMemsetAsync(cnt_p, 0, sizeof(int), 0);
    cudaEventRecord(evFork, 0);
    cudaStreamWaitEvent(s1, evFork, 0);

    k_build<<<BB, HH>>>(gids, lengths);
    cudaEventRecord(evBuild, 0);

    // side stream: w1 transpose (needed by mma0), then w2 transpose + base (needed by mma1)
    k_transpose<<<dim3(ND1 / 32, KD1 / 32), dim3(32, 8), 0, s1>>>(w1, w1t_p, KD1, ND1);
    cudaEventRecord(evT1, s1);
    k_transpose<<<dim3(ND2 / 32, ND1 / 32), dim3(32, 8), 0, s1>>>(w2, w2t_p, ND1, ND2);
    cudaStreamWaitEvent(s1, evBuild, 0);
    k_base<<<BB * SS * LL / 4, 128, 0, s1>>>(pos_emb, seq_emb, empty_tok, out, write_mask);
    cudaEventRecord(evSide, s1);

    // main stream continues
    k_gather_ln<<<MAXM, 128>>>(embed, tg_emb, gamma, beta, ht, pt, at, ct, tgap);
    cudaStreamWaitEvent(0, evT1, 0);
    k_mma<0><<<dim3(ND1 / 128, MAXM / 128), 256, GSMEM_BYTES>>>(w1t_p, b1, nullptr);
    cudaStreamWaitEvent(0, evSide, 0);
    k_mma<1><<<dim3(ND2 / 128, MAXM / 128), 256, GSMEM_BYTES>>>(w2t_p, b2, out);
}